// round 7
// baseline (speedup 1.0000x reference)
#include <cuda_runtime.h>
#include <cuda_fp16.h>

#define N_NODES     50000
#define N_EDGES     800000
#define HIDDEN      128
#define F_IN        11
#define NUM_CLASSES 19
#define NUM_GRAPHS  2048

#define SCAN_B      256
#define N_SBLK      ((N_NODES + SCAN_B - 1) / SCAN_B)   // 196

// ---- scratch ----
__device__ __align__(16) __half g_h16[N_NODES * HIDDEN];  // fp16 h (layers 1,2)
__device__ __align__(16) float g_h[N_NODES * HIDDEN];     // fp32 h (layer 3 out)
__device__ __align__(16) float g_agg[N_NODES * HIDDEN];
__device__ __align__(16) float g_agg11[N_NODES * 12];
__device__ float g_dinv[N_NODES];
__device__ int   g_counts[N_NODES];
__device__ int   g_fill[N_NODES];
__device__ int   g_rowptr[N_NODES + 1];
__device__ int   g_bsum[N_SBLK];
__device__ int   g_boff[N_SBLK];
__device__ __align__(16) int2 g_edge[N_EDGES];            // (col, norm bits)
__device__ __align__(16) float g_Wt2[HIDDEN * HIDDEN];
__device__ __align__(16) float g_Wt3[HIDDEN * HIDDEN];
__device__ float g_pool[NUM_GRAPHS * HIDDEN];
__device__ int   g_gcnt[NUM_GRAPHS];
__device__ int   g_gstart[NUM_GRAPHS + 1];

__device__ __forceinline__ int clampi(int v, int hi) {
    return v < 0 ? 0 : (v >= hi ? hi - 1 : v);
}

// ---------------------------------------------------------------------------
__global__ void k_zero() {
    int i = blockIdx.x * blockDim.x + threadIdx.x;
    if (i < N_NODES) { g_counts[i] = 0; g_fill[i] = 0; }
    if (i < NUM_GRAPHS) g_gcnt[i] = 0;
}

__global__ void k_deg(const int* __restrict__ ei) {
    int e = blockIdx.x * blockDim.x + threadIdx.x;
    if (e < N_EDGES) atomicAdd(&g_counts[clampi(ei[N_EDGES + e], N_NODES)], 1);
}

// fused: dinv + per-graph node counts + W2/W3 transpose
__global__ void k_node_setup(const int* __restrict__ batch,
                             const float* __restrict__ W2,
                             const float* __restrict__ W3) {
    int i = blockIdx.x * blockDim.x + threadIdx.x;
    if (i < N_NODES) {
        g_dinv[i] = rsqrtf((float)g_counts[i] + 1.0f);
        atomicAdd(&g_gcnt[clampi(batch[i], NUM_GRAPHS)], 1);
    }
    if (i < HIDDEN * HIDDEN) {
        int k = i / HIDDEN, c = i % HIDDEN;
        g_Wt2[c * HIDDEN + k] = W2[i];
        g_Wt3[c * HIDDEN + k] = W3[i];
    }
}

// ---- 2-level scan of g_counts -> g_rowptr ----
__global__ void k_bsum() {
    __shared__ int s[SCAN_B];
    int t = threadIdx.x;
    int i = blockIdx.x * SCAN_B + t;
    s[t] = (i < N_NODES) ? g_counts[i] : 0;
    __syncthreads();
    for (int off = SCAN_B / 2; off > 0; off >>= 1) {
        if (t < off) s[t] += s[t + off];
        __syncthreads();
    }
    if (t == 0) g_bsum[blockIdx.x] = s[0];
}

__global__ void k_scan_mid() {
    __shared__ int s[1024];
    int t = threadIdx.x;
    if (blockIdx.x == 0) {
        if (t < SCAN_B) s[t] = (t < N_SBLK) ? g_bsum[t] : 0;
        __syncthreads();
        for (int off = 1; off < SCAN_B; off <<= 1) {
            int v = (t >= off && t < SCAN_B) ? s[t - off] : 0;
            __syncthreads();
            if (t < SCAN_B) s[t] += v;
            __syncthreads();
        }
        if (t < N_SBLK) g_boff[t] = (t == 0) ? 0 : s[t - 1];
    } else {
        int c0 = g_gcnt[2 * t], c1 = g_gcnt[2 * t + 1];
        s[t] = c0 + c1;
        __syncthreads();
        for (int off = 1; off < 1024; off <<= 1) {
            int v = (t >= off) ? s[t - off] : 0;
            __syncthreads();
            s[t] += v;
            __syncthreads();
        }
        int excl = s[t] - (c0 + c1);
        g_gstart[2 * t] = excl;
        g_gstart[2 * t + 1] = excl + c0;
        if (t == 1023) g_gstart[NUM_GRAPHS] = s[1023];
    }
}

__global__ void k_rowptr() {
    __shared__ int s[SCAN_B];
    int t = threadIdx.x;
    int i = blockIdx.x * SCAN_B + t;
    int c = (i < N_NODES) ? g_counts[i] : 0;
    s[t] = c;
    __syncthreads();
    for (int off = 1; off < SCAN_B; off <<= 1) {
        int v = (t >= off) ? s[t - off] : 0;
        __syncthreads();
        s[t] += v;
        __syncthreads();
    }
    if (i < N_NODES) g_rowptr[i] = g_boff[blockIdx.x] + s[t] - c;
    if (i == N_NODES - 1) g_rowptr[N_NODES] = N_EDGES;
}

__global__ void k_scatter(const int* __restrict__ ei) {
    int e = blockIdx.x * blockDim.x + threadIdx.x;
    if (e >= N_EDGES) return;
    int s = clampi(ei[e], N_NODES);
    int d = clampi(ei[N_EDGES + e], N_NODES);
    int pos = g_rowptr[d] + atomicAdd(&g_fill[d], 1);
    g_edge[pos] = make_int2(s, __float_as_int(g_dinv[s] * g_dinv[d]));
}

// aggregate raw x (11-dim): thread per (node, feature)
__global__ void k_agg11(const float* __restrict__ x) {
    int gid = blockIdx.x * blockDim.x + threadIdx.x;
    int node = gid >> 4;
    int f = gid & 15;
    if (node >= N_NODES || f >= F_IN) return;
    int s = g_rowptr[node], e = g_rowptr[node + 1];
    float acc = 0.0f;
    for (int i = s; i < e; i++) {
        int2 ed = g_edge[i];
        acc += x[ed.x * F_IN + f] * __int_as_float(ed.y);
    }
    float di = g_dinv[node];
    acc += x[node * F_IN + f] * (di * di);
    g_agg11[node * 12 + f] = acc;
}

// h1 = relu(agg11 @ W1 + b1) -> fp16
__global__ void k_gemm11(const float* __restrict__ W1, const float* __restrict__ b1) {
    __shared__ float Ws[F_IN * HIDDEN];
    __shared__ float xs[32][12];
    int t = threadIdx.x;
    int node0 = blockIdx.x * 32;
    for (int i = t; i < F_IN * HIDDEN; i += 128) Ws[i] = W1[i];
    for (int i = t; i < 32 * 12; i += 128) {
        int r = i / 12, f = i % 12;
        int n = node0 + r;
        xs[r][f] = (n < N_NODES) ? g_agg11[n * 12 + f] : 0.0f;
    }
    __syncthreads();
    float bb = b1[t];
    for (int n = 0; n < 32; n++) {
        int node = node0 + n;
        if (node >= N_NODES) break;
        float acc = bb;
#pragma unroll
        for (int k = 0; k < F_IN; k++)
            acc += xs[n][k] * Ws[k * HIDDEN + t];
        g_h16[node * HIDDEN + t] = __float2half(fmaxf(acc, 0.0f));
    }
}

// aggregate 128-dim fp16 features: warp per node, lane owns 4 features (8B)
__global__ void k_agg128() {
    int gid = blockIdx.x * blockDim.x + threadIdx.x;
    int node = gid >> 5;
    int lane = gid & 31;
    if (node >= N_NODES) return;
    int s = g_rowptr[node], e = g_rowptr[node + 1];
    const uint2* __restrict__ h2 = (const uint2*)g_h16;
    float4 acc = make_float4(0.f, 0.f, 0.f, 0.f);
    for (int i = s; i < e; i++) {
        int2 ed = g_edge[i];
        float w = __int_as_float(ed.y);
        uint2 v = h2[ed.x * 32 + lane];
        float2 fa = __half22float2(*(const __half2*)&v.x);
        float2 fb = __half22float2(*(const __half2*)&v.y);
        acc.x += w * fa.x; acc.y += w * fa.y; acc.z += w * fb.x; acc.w += w * fb.y;
    }
    float di = g_dinv[node];
    float w = di * di;
    uint2 v = h2[node * 32 + lane];
    float2 fa = __half22float2(*(const __half2*)&v.x);
    float2 fb = __half22float2(*(const __half2*)&v.y);
    acc.x += w * fa.x; acc.y += w * fa.y; acc.z += w * fb.x; acc.w += w * fb.y;
    ((float4*)g_agg)[node * 32 + lane] = acc;
}

// h = [relu](agg @ W + b) via fma.rn.f32x2.
// which_w: 0 -> W2^T, relu, fp16 out; 1 -> W3^T, no relu, fp32 out.
__global__ void k_gemm128_f2(const float* __restrict__ b, int which_w) {
    __shared__ __align__(16) float2 xs2[16][HIDDEN];   // 16 KB
    const float* __restrict__ Wt = which_w ? g_Wt3 : g_Wt2;
    int col = threadIdx.x;
    int row0 = blockIdx.x * 32;

    for (int i = col; i < 512; i += 128) {
        int p = i >> 5, kk = i & 31;
        int n0 = row0 + 2 * p, n1 = n0 + 1;
        float4 a = (n0 < N_NODES) ? ((const float4*)g_agg)[n0 * 32 + kk]
                                  : make_float4(0.f, 0.f, 0.f, 0.f);
        float4 c = (n1 < N_NODES) ? ((const float4*)g_agg)[n1 * 32 + kk]
                                  : make_float4(0.f, 0.f, 0.f, 0.f);
        float4* dst = (float4*)&xs2[p][4 * kk];
        dst[0] = make_float4(a.x, c.x, a.y, c.y);
        dst[1] = make_float4(a.z, c.z, a.w, c.w);
    }
    __syncthreads();

    unsigned long long acc[16];
    float bb = b[col];
    unsigned long long bb2;
    asm("mov.b64 %0, {%1, %1};" : "=l"(bb2) : "f"(bb));
#pragma unroll
    for (int p = 0; p < 16; p++) acc[p] = bb2;

    const float4* __restrict__ wt4 = (const float4*)(Wt + col * HIDDEN);
    for (int kk = 0; kk < 32; kk++) {
        float4 w = wt4[kk];
        unsigned long long w0, w1, w2, w3;
        asm("mov.b64 %0, {%1, %1};" : "=l"(w0) : "f"(w.x));
        asm("mov.b64 %0, {%1, %1};" : "=l"(w1) : "f"(w.y));
        asm("mov.b64 %0, {%1, %1};" : "=l"(w2) : "f"(w.z));
        asm("mov.b64 %0, {%1, %1};" : "=l"(w3) : "f"(w.w));
#pragma unroll
        for (int p = 0; p < 16; p++) {
            ulonglong2 xa = *(const ulonglong2*)&xs2[p][4 * kk];
            ulonglong2 xb = *(const ulonglong2*)&xs2[p][4 * kk + 2];
            asm("fma.rn.f32x2 %0, %1, %2, %0;" : "+l"(acc[p]) : "l"(xa.x), "l"(w0));
            asm("fma.rn.f32x2 %0, %1, %2, %0;" : "+l"(acc[p]) : "l"(xa.y), "l"(w1));
            asm("fma.rn.f32x2 %0, %1, %2, %0;" : "+l"(acc[p]) : "l"(xb.x), "l"(w2));
            asm("fma.rn.f32x2 %0, %1, %2, %0;" : "+l"(acc[p]) : "l"(xb.y), "l"(w3));
        }
    }

#pragma unroll
    for (int p = 0; p < 16; p++) {
        float lo, hi;
        asm("mov.b64 {%0, %1}, %2;" : "=f"(lo), "=f"(hi) : "l"(acc[p]));
        int n0 = row0 + 2 * p, n1 = n0 + 1;
        if (which_w == 0) {
            lo = fmaxf(lo, 0.0f); hi = fmaxf(hi, 0.0f);
            if (n0 < N_NODES) g_h16[n0 * HIDDEN + col] = __float2half(lo);
            if (n1 < N_NODES) g_h16[n1 * HIDDEN + col] = __float2half(hi);
        } else {
            if (n0 < N_NODES) g_h[n0 * HIDDEN + col] = lo;
            if (n1 < N_NODES) g_h[n1 * HIDDEN + col] = hi;
        }
    }
}

// segmented mean-pool over fp32 layer-3 output
__global__ void k_pool_seg() {
    int g = blockIdx.x;
    int t = threadIdx.x;
    int s = g_gstart[g], e = g_gstart[g + 1];
    float acc = 0.0f;
    for (int n = s; n < e; n++)
        acc += g_h[n * HIDDEN + t];
    g_pool[g * HIDDEN + t] = acc / fmaxf((float)(e - s), 1.0f);
}

__global__ void k_final(const float* __restrict__ Wl, const float* __restrict__ bl,
                        float* __restrict__ out) {
    __shared__ float ps[HIDDEN];
    int g = blockIdx.x;
    int t = threadIdx.x;
    ps[t] = g_pool[g * HIDDEN + t];
    __syncthreads();
    if (t < NUM_CLASSES) {
        float acc = bl[t];
#pragma unroll 8
        for (int h = 0; h < HIDDEN; h++)
            acc += ps[h] * Wl[h * NUM_CLASSES + t];
        out[g * NUM_CLASSES + t] = acc;
    }
}

// ---------------------------------------------------------------------------
extern "C" void kernel_launch(void* const* d_in, const int* in_sizes, int n_in,
                              void* d_out, int out_size) {
    const float* x     = (const float*)d_in[0];
    const int*   ei    = (const int*)d_in[1];
    const int*   batch = (const int*)d_in[2];
    const float* W1 = (const float*)d_in[3];
    const float* b1 = (const float*)d_in[4];
    const float* W2 = (const float*)d_in[5];
    const float* b2 = (const float*)d_in[6];
    const float* W3 = (const float*)d_in[7];
    const float* b3 = (const float*)d_in[8];
    const float* Wl = (const float*)d_in[9];
    const float* bl = (const float*)d_in[10];
    float* out = (float*)d_out;

    k_zero<<<(N_NODES + 255) / 256, 256>>>();

    // CSR build + weight prep
    k_deg<<<(N_EDGES + 255) / 256, 256>>>(ei);
    k_node_setup<<<(N_NODES + 255) / 256, 256>>>(batch, W2, W3);
    k_bsum<<<N_SBLK, SCAN_B>>>();
    k_scan_mid<<<2, 1024>>>();
    k_rowptr<<<N_SBLK, SCAN_B>>>();
    k_scatter<<<(N_EDGES + 255) / 256, 256>>>(ei);

    // Layer 1: aggregate in 11 dims, then GEMM
    k_agg11<<<(N_NODES * 16 + 255) / 256, 256>>>(x);
    k_gemm11<<<(N_NODES + 31) / 32, 128>>>(W1, b1);

    // Layer 2
    k_agg128<<<(N_NODES * 32 + 255) / 256, 256>>>();
    k_gemm128_f2<<<(N_NODES + 31) / 32, 128>>>(b2, 0);

    // Layer 3 (no relu, fp32 out)
    k_agg128<<<(N_NODES * 32 + 255) / 256, 256>>>();
    k_gemm128_f2<<<(N_NODES + 31) / 32, 128>>>(b3, 1);

    // Pool + head
    k_pool_seg<<<NUM_GRAPHS, HIDDEN>>>();
    k_final<<<NUM_GRAPHS, 128>>>(Wl, bl, out);
}

// round 8
// speedup vs baseline: 1.0271x; 1.0271x over previous
#include <cuda_runtime.h>
#include <cuda_fp16.h>

#define N_NODES     50000
#define N_EDGES     800000
#define HIDDEN      128
#define F_IN        11
#define NUM_CLASSES 19
#define NUM_GRAPHS  2048

#define SCAN_B      256
#define N_SBLK      ((N_NODES + SCAN_B - 1) / SCAN_B)   // 196

// ---- scratch ----
__device__ __align__(16) __half g_h16[N_NODES * HIDDEN];  // fp16 h (layers 1,2)
__device__ __align__(16) float g_h[N_NODES * HIDDEN];     // fp32 h (layer 3 out)
__device__ __align__(16) float g_agg[N_NODES * HIDDEN];
__device__ __align__(16) float g_agg11[N_NODES * 12];
__device__ float g_dinv[N_NODES];
__device__ int   g_counts[N_NODES];
__device__ int   g_fill[N_NODES];
__device__ int   g_rowptr[N_NODES + 1];
__device__ int   g_bsum[N_SBLK];
__device__ int   g_boff[N_SBLK];
__device__ __align__(16) int2 g_edge[N_EDGES];            // (col, norm bits)
__device__ __align__(16) float g_Wt2[HIDDEN * HIDDEN];
__device__ __align__(16) float g_Wt3[HIDDEN * HIDDEN];
__device__ float g_pool[NUM_GRAPHS * HIDDEN];
__device__ int   g_gcnt[NUM_GRAPHS];
__device__ int   g_gstart[NUM_GRAPHS + 1];

__device__ __forceinline__ int clampi(int v, int hi) {
    return v < 0 ? 0 : (v >= hi ? hi - 1 : v);
}

__device__ __forceinline__ void fma_h2(float4& acc, uint2 v, float w) {
    float2 fa = __half22float2(*(const __half2*)&v.x);
    float2 fb = __half22float2(*(const __half2*)&v.y);
    acc.x += w * fa.x; acc.y += w * fa.y; acc.z += w * fb.x; acc.w += w * fb.y;
}

// ---------------------------------------------------------------------------
__global__ void k_zero() {
    int i = blockIdx.x * blockDim.x + threadIdx.x;
    if (i < N_NODES) { g_counts[i] = 0; g_fill[i] = 0; }
    if (i < NUM_GRAPHS) g_gcnt[i] = 0;
}

__global__ void k_deg(const int* __restrict__ ei) {
    int e = blockIdx.x * blockDim.x + threadIdx.x;
    if (e < N_EDGES) atomicAdd(&g_counts[clampi(ei[N_EDGES + e], N_NODES)], 1);
}

// fused: dinv + per-graph node counts + W2/W3 transpose
__global__ void k_node_setup(const int* __restrict__ batch,
                             const float* __restrict__ W2,
                             const float* __restrict__ W3) {
    int i = blockIdx.x * blockDim.x + threadIdx.x;
    if (i < N_NODES) {
        g_dinv[i] = rsqrtf((float)g_counts[i] + 1.0f);
        atomicAdd(&g_gcnt[clampi(batch[i], NUM_GRAPHS)], 1);
    }
    if (i < HIDDEN * HIDDEN) {
        int k = i / HIDDEN, c = i % HIDDEN;
        g_Wt2[c * HIDDEN + k] = W2[i];
        g_Wt3[c * HIDDEN + k] = W3[i];
    }
}

// ---- 2-level scan of g_counts -> g_rowptr ----
__global__ void k_bsum() {
    __shared__ int s[SCAN_B];
    int t = threadIdx.x;
    int i = blockIdx.x * SCAN_B + t;
    s[t] = (i < N_NODES) ? g_counts[i] : 0;
    __syncthreads();
    for (int off = SCAN_B / 2; off > 0; off >>= 1) {
        if (t < off) s[t] += s[t + off];
        __syncthreads();
    }
    if (t == 0) g_bsum[blockIdx.x] = s[0];
}

__global__ void k_scan_mid() {
    __shared__ int s[1024];
    int t = threadIdx.x;
    if (blockIdx.x == 0) {
        if (t < SCAN_B) s[t] = (t < N_SBLK) ? g_bsum[t] : 0;
        __syncthreads();
        for (int off = 1; off < SCAN_B; off <<= 1) {
            int v = (t >= off && t < SCAN_B) ? s[t - off] : 0;
            __syncthreads();
            if (t < SCAN_B) s[t] += v;
            __syncthreads();
        }
        if (t < N_SBLK) g_boff[t] = (t == 0) ? 0 : s[t - 1];
    } else {
        int c0 = g_gcnt[2 * t], c1 = g_gcnt[2 * t + 1];
        s[t] = c0 + c1;
        __syncthreads();
        for (int off = 1; off < 1024; off <<= 1) {
            int v = (t >= off) ? s[t - off] : 0;
            __syncthreads();
            s[t] += v;
            __syncthreads();
        }
        int excl = s[t] - (c0 + c1);
        g_gstart[2 * t] = excl;
        g_gstart[2 * t + 1] = excl + c0;
        if (t == 1023) g_gstart[NUM_GRAPHS] = s[1023];
    }
}

__global__ void k_rowptr() {
    __shared__ int s[SCAN_B];
    int t = threadIdx.x;
    int i = blockIdx.x * SCAN_B + t;
    int c = (i < N_NODES) ? g_counts[i] : 0;
    s[t] = c;
    __syncthreads();
    for (int off = 1; off < SCAN_B; off <<= 1) {
        int v = (t >= off) ? s[t - off] : 0;
        __syncthreads();
        s[t] += v;
        __syncthreads();
    }
    if (i < N_NODES) g_rowptr[i] = g_boff[blockIdx.x] + s[t] - c;
    if (i == N_NODES - 1) g_rowptr[N_NODES] = N_EDGES;
}

__global__ void k_scatter(const int* __restrict__ ei) {
    int e = blockIdx.x * blockDim.x + threadIdx.x;
    if (e >= N_EDGES) return;
    int s = clampi(ei[e], N_NODES);
    int d = clampi(ei[N_EDGES + e], N_NODES);
    int pos = g_rowptr[d] + atomicAdd(&g_fill[d], 1);
    g_edge[pos] = make_int2(s, __float_as_int(g_dinv[s] * g_dinv[d]));
}

// aggregate raw x (11-dim): thread per (node, feature); 4-deep MLP pipeline
__global__ void k_agg11(const float* __restrict__ x) {
    int gid = blockIdx.x * blockDim.x + threadIdx.x;
    int node = gid >> 4;
    int f = gid & 15;
    if (node >= N_NODES || f >= F_IN) return;
    int s = g_rowptr[node], e = g_rowptr[node + 1];
    float acc = 0.0f;
    int i = s;
    for (; i + 4 <= e; i += 4) {
        int2 e0 = g_edge[i], e1 = g_edge[i + 1], e2 = g_edge[i + 2], e3 = g_edge[i + 3];
        float x0 = x[e0.x * F_IN + f];
        float x1 = x[e1.x * F_IN + f];
        float x2 = x[e2.x * F_IN + f];
        float x3 = x[e3.x * F_IN + f];
        acc += x0 * __int_as_float(e0.y) + x1 * __int_as_float(e1.y)
             + x2 * __int_as_float(e2.y) + x3 * __int_as_float(e3.y);
    }
    for (; i < e; i++) {
        int2 ed = g_edge[i];
        acc += x[ed.x * F_IN + f] * __int_as_float(ed.y);
    }
    float di = g_dinv[node];
    acc += x[node * F_IN + f] * (di * di);
    g_agg11[node * 12 + f] = acc;
}

// h1 = relu(agg11 @ W1 + b1) -> fp16
__global__ void k_gemm11(const float* __restrict__ W1, const float* __restrict__ b1) {
    __shared__ float Ws[F_IN * HIDDEN];
    __shared__ float xs[32][12];
    int t = threadIdx.x;
    int node0 = blockIdx.x * 32;
    for (int i = t; i < F_IN * HIDDEN; i += 128) Ws[i] = W1[i];
    for (int i = t; i < 32 * 12; i += 128) {
        int r = i / 12, f = i % 12;
        int n = node0 + r;
        xs[r][f] = (n < N_NODES) ? g_agg11[n * 12 + f] : 0.0f;
    }
    __syncthreads();
    float bb = b1[t];
    for (int n = 0; n < 32; n++) {
        int node = node0 + n;
        if (node >= N_NODES) break;
        float acc = bb;
#pragma unroll
        for (int k = 0; k < F_IN; k++)
            acc += xs[n][k] * Ws[k * HIDDEN + t];
        g_h16[node * HIDDEN + t] = __float2half(fmaxf(acc, 0.0f));
    }
}

// aggregate 128-dim fp16 features: warp per node, 4-deep MLP pipeline
__global__ void k_agg128() {
    int gid = blockIdx.x * blockDim.x + threadIdx.x;
    int node = gid >> 5;
    int lane = gid & 31;
    if (node >= N_NODES) return;
    int s = g_rowptr[node], e = g_rowptr[node + 1];
    const uint2* __restrict__ h2 = (const uint2*)g_h16;
    float4 acc = make_float4(0.f, 0.f, 0.f, 0.f);
    int i = s;
    for (; i + 4 <= e; i += 4) {
        int2 e0 = g_edge[i], e1 = g_edge[i + 1], e2 = g_edge[i + 2], e3 = g_edge[i + 3];
        uint2 v0 = h2[e0.x * 32 + lane];
        uint2 v1 = h2[e1.x * 32 + lane];
        uint2 v2 = h2[e2.x * 32 + lane];
        uint2 v3 = h2[e3.x * 32 + lane];
        fma_h2(acc, v0, __int_as_float(e0.y));
        fma_h2(acc, v1, __int_as_float(e1.y));
        fma_h2(acc, v2, __int_as_float(e2.y));
        fma_h2(acc, v3, __int_as_float(e3.y));
    }
    for (; i < e; i++) {
        int2 ed = g_edge[i];
        uint2 v = h2[ed.x * 32 + lane];
        fma_h2(acc, v, __int_as_float(ed.y));
    }
    float di = g_dinv[node];
    uint2 v = h2[node * 32 + lane];
    fma_h2(acc, v, di * di);
    ((float4*)g_agg)[node * 32 + lane] = acc;
}

// h = [relu](agg @ W + b) via fma.rn.f32x2.
// which_w: 0 -> W2^T, relu, fp16 out; 1 -> W3^T, no relu, fp32 out.
__global__ void k_gemm128_f2(const float* __restrict__ b, int which_w) {
    __shared__ __align__(16) float2 xs2[16][HIDDEN];   // 16 KB
    const float* __restrict__ Wt = which_w ? g_Wt3 : g_Wt2;
    int col = threadIdx.x;
    int row0 = blockIdx.x * 32;

    for (int i = col; i < 512; i += 128) {
        int p = i >> 5, kk = i & 31;
        int n0 = row0 + 2 * p, n1 = n0 + 1;
        float4 a = (n0 < N_NODES) ? ((const float4*)g_agg)[n0 * 32 + kk]
                                  : make_float4(0.f, 0.f, 0.f, 0.f);
        float4 c = (n1 < N_NODES) ? ((const float4*)g_agg)[n1 * 32 + kk]
                                  : make_float4(0.f, 0.f, 0.f, 0.f);
        float4* dst = (float4*)&xs2[p][4 * kk];
        dst[0] = make_float4(a.x, c.x, a.y, c.y);
        dst[1] = make_float4(a.z, c.z, a.w, c.w);
    }
    __syncthreads();

    unsigned long long acc[16];
    float bb = b[col];
    unsigned long long bb2;
    asm("mov.b64 %0, {%1, %1};" : "=l"(bb2) : "f"(bb));
#pragma unroll
    for (int p = 0; p < 16; p++) acc[p] = bb2;

    const float4* __restrict__ wt4 = (const float4*)(Wt + col * HIDDEN);
    for (int kk = 0; kk < 32; kk++) {
        float4 w = wt4[kk];
        unsigned long long w0, w1, w2, w3;
        asm("mov.b64 %0, {%1, %1};" : "=l"(w0) : "f"(w.x));
        asm("mov.b64 %0, {%1, %1};" : "=l"(w1) : "f"(w.y));
        asm("mov.b64 %0, {%1, %1};" : "=l"(w2) : "f"(w.z));
        asm("mov.b64 %0, {%1, %1};" : "=l"(w3) : "f"(w.w));
#pragma unroll
        for (int p = 0; p < 16; p++) {
            ulonglong2 xa = *(const ulonglong2*)&xs2[p][4 * kk];
            ulonglong2 xb = *(const ulonglong2*)&xs2[p][4 * kk + 2];
            asm("fma.rn.f32x2 %0, %1, %2, %0;" : "+l"(acc[p]) : "l"(xa.x), "l"(w0));
            asm("fma.rn.f32x2 %0, %1, %2, %0;" : "+l"(acc[p]) : "l"(xa.y), "l"(w1));
            asm("fma.rn.f32x2 %0, %1, %2, %0;" : "+l"(acc[p]) : "l"(xb.x), "l"(w2));
            asm("fma.rn.f32x2 %0, %1, %2, %0;" : "+l"(acc[p]) : "l"(xb.y), "l"(w3));
        }
    }

#pragma unroll
    for (int p = 0; p < 16; p++) {
        float lo, hi;
        asm("mov.b64 {%0, %1}, %2;" : "=f"(lo), "=f"(hi) : "l"(acc[p]));
        int n0 = row0 + 2 * p, n1 = n0 + 1;
        if (which_w == 0) {
            lo = fmaxf(lo, 0.0f); hi = fmaxf(hi, 0.0f);
            if (n0 < N_NODES) g_h16[n0 * HIDDEN + col] = __float2half(lo);
            if (n1 < N_NODES) g_h16[n1 * HIDDEN + col] = __float2half(hi);
        } else {
            if (n0 < N_NODES) g_h[n0 * HIDDEN + col] = lo;
            if (n1 < N_NODES) g_h[n1 * HIDDEN + col] = hi;
        }
    }
}

// segmented mean-pool over fp32 layer-3 output
__global__ void k_pool_seg() {
    int g = blockIdx.x;
    int t = threadIdx.x;
    int s = g_gstart[g], e = g_gstart[g + 1];
    float acc = 0.0f;
    for (int n = s; n < e; n++)
        acc += g_h[n * HIDDEN + t];
    g_pool[g * HIDDEN + t] = acc / fmaxf((float)(e - s), 1.0f);
}

__global__ void k_final(const float* __restrict__ Wl, const float* __restrict__ bl,
                        float* __restrict__ out) {
    __shared__ float ps[HIDDEN];
    int g = blockIdx.x;
    int t = threadIdx.x;
    ps[t] = g_pool[g * HIDDEN + t];
    __syncthreads();
    if (t < NUM_CLASSES) {
        float acc = bl[t];
#pragma unroll 8
        for (int h = 0; h < HIDDEN; h++)
            acc += ps[h] * Wl[h * NUM_CLASSES + t];
        out[g * NUM_CLASSES + t] = acc;
    }
}

// ---------------------------------------------------------------------------
extern "C" void kernel_launch(void* const* d_in, const int* in_sizes, int n_in,
                              void* d_out, int out_size) {
    const float* x     = (const float*)d_in[0];
    const int*   ei    = (const int*)d_in[1];
    const int*   batch = (const int*)d_in[2];
    const float* W1 = (const float*)d_in[3];
    const float* b1 = (const float*)d_in[4];
    const float* W2 = (const float*)d_in[5];
    const float* b2 = (const float*)d_in[6];
    const float* W3 = (const float*)d_in[7];
    const float* b3 = (const float*)d_in[8];
    const float* Wl = (const float*)d_in[9];
    const float* bl = (const float*)d_in[10];
    float* out = (float*)d_out;

    k_zero<<<(N_NODES + 255) / 256, 256>>>();

    // CSR build + weight prep
    k_deg<<<(N_EDGES + 255) / 256, 256>>>(ei);
    k_node_setup<<<(N_NODES + 255) / 256, 256>>>(batch, W2, W3);
    k_bsum<<<N_SBLK, SCAN_B>>>();
    k_scan_mid<<<2, 1024>>>();
    k_rowptr<<<N_SBLK, SCAN_B>>>();
    k_scatter<<<(N_EDGES + 255) / 256, 256>>>(ei);

    // Layer 1: aggregate in 11 dims, then GEMM
    k_agg11<<<(N_NODES * 16 + 255) / 256, 256>>>(x);
    k_gemm11<<<(N_NODES + 31) / 32, 128>>>(W1, b1);

    // Layer 2
    k_agg128<<<(N_NODES * 32 + 255) / 256, 256>>>();
    k_gemm128_f2<<<(N_NODES + 31) / 32, 128>>>(b2, 0);

    // Layer 3 (no relu, fp32 out)
    k_agg128<<<(N_NODES * 32 + 255) / 256, 256>>>();
    k_gemm128_f2<<<(N_NODES + 31) / 32, 128>>>(b3, 1);

    // Pool + head
    k_pool_seg<<<NUM_GRAPHS, HIDDEN>>>();
    k_final<<<NUM_GRAPHS, 128>>>(Wl, bl, out);
}